// round 7
// baseline (speedup 1.0000x reference)
#include <cuda_runtime.h>
#include <cstdint>

#define N_PTS   4096
#define DIM     128
#define TOPK    4

// ---------------- global scratch ----------------
__device__ float Z_buf[2 * N_PTS * DIM];        // x @ W   (4 MB)
__device__ float Top5_buf[2 * N_PTS * 10];      // per (row, half) top-5 packed keys

// ---------------- kernel A: Z = x @ W (W streamed via L2, x in smem) ----------------
#define GA_THREADS 256
#define GA_ROWS    32          // 8 warps x 4 rows

__global__ void __launch_bounds__(GA_THREADS, 8)
gemm_xw(const float* __restrict__ x, const float* __restrict__ W)
{
    __shared__ float x_s[GA_ROWS * DIM];        // 16 KB

    const int tid = threadIdx.x;
    const int g0  = blockIdx.x * GA_ROWS;

    const float4* xg = (const float4*)x + (size_t)g0 * 32;
    float4* xs4 = (float4*)x_s;
    #pragma unroll
    for (int i = tid; i < GA_ROWS * 32; i += GA_THREADS) xs4[i] = xg[i];
    __syncthreads();

    const int warp = tid >> 5;
    const int lane = tid & 31;
    const float* xr = x_s + warp * 4 * DIM;
    const float4* W4 = (const float4*)W;

    float4 a0 = make_float4(0.f,0.f,0.f,0.f);
    float4 a1 = a0, a2 = a0, a3 = a0;

    #pragma unroll 4
    for (int d = 0; d < DIM; d++) {
        float4 wv = __ldg(&W4[d * 32 + lane]);  // L1/L2-resident stream
        float y0 = xr[d];
        float y1 = xr[d + DIM];
        float y2 = xr[d + 2*DIM];
        float y3 = xr[d + 3*DIM];
        a0.x = fmaf(y0, wv.x, a0.x); a0.y = fmaf(y0, wv.y, a0.y);
        a0.z = fmaf(y0, wv.z, a0.z); a0.w = fmaf(y0, wv.w, a0.w);
        a1.x = fmaf(y1, wv.x, a1.x); a1.y = fmaf(y1, wv.y, a1.y);
        a1.z = fmaf(y1, wv.z, a1.z); a1.w = fmaf(y1, wv.w, a1.w);
        a2.x = fmaf(y2, wv.x, a2.x); a2.y = fmaf(y2, wv.y, a2.y);
        a2.z = fmaf(y2, wv.z, a2.z); a2.w = fmaf(y2, wv.w, a2.w);
        a3.x = fmaf(y3, wv.x, a3.x); a3.y = fmaf(y3, wv.y, a3.y);
        a3.z = fmaf(y3, wv.z, a3.z); a3.w = fmaf(y3, wv.w, a3.w);
    }

    float4* Z4 = (float4*)Z_buf;
    const size_t r = (size_t)g0 + warp * 4;
    Z4[(r + 0) * 32 + lane] = a0;
    Z4[(r + 1) * 32 + lane] = a1;
    Z4[(r + 2) * 32 + lane] = a2;
    Z4[(r + 3) * 32 + lane] = a3;
}

// ---------------- kernel B: per-(32-row, 2048-cand-half) top-5 scan ----------------
// blockIdx.x -> (row_group, half). 16 warps; row-per-lane; slice 128 cands/warp.
// Phase 1: first 64 unconditional bubble -> tau (5th of 1024 samples of the half).
// Phase 2: last 64 filtered. Tree-merge; warp 0 writes 5 packed keys per row.

#define SB_THREADS 512
#define SB_WARPS   16
#define HALF_C     (N_PTS / 2)              // 2048
#define SB_SLICE   (HALF_C / SB_WARPS)      // 128
#define SB_L1      64

#define BUBBLE5(k)                                            \
    { float _t, _k = (k);                                     \
      _t = fminf(s0, _k); _k = fmaxf(s0, _k); s0 = _t;        \
      _t = fminf(s1, _k); _k = fmaxf(s1, _k); s1 = _t;        \
      _t = fminf(s2, _k); _k = fmaxf(s2, _k); s2 = _t;        \
      _t = fminf(s3, _k); _k = fmaxf(s3, _k); s3 = _t;        \
      s4 = fminf(s4, _k); }

#define TREEMERGE()                                                        \
    _Pragma("unroll")                                                      \
    for (int step = 8; step >= 1; step >>= 1) {                            \
        if (warp >= step && warp < 2 * step) {                             \
            float* m = m_s + ((warp - step) * 32 + lane) * 5;              \
            m[0] = s0; m[1] = s1; m[2] = s2; m[3] = s3; m[4] = s4;         \
        }                                                                  \
        __syncthreads();                                                   \
        if (warp < step) {                                                 \
            const float* m = m_s + (warp * 32 + lane) * 5;                 \
            BUBBLE5(m[0]); BUBBLE5(m[1]); BUBBLE5(m[2]);                   \
            BUBBLE5(m[3]); BUBBLE5(m[4]);                                  \
        }                                                                  \
        __syncthreads();                                                   \
    }

__global__ void __launch_bounds__(SB_THREADS, 4)
scan_topk(const float* __restrict__ pos)
{
    extern __shared__ float smemB[];
    float4* pos_s  = (float4*)smemB;                   // [2048] .w = -0.5*|p|^2
    float*  m_s    = (float*)(pos_s + HALF_C);         // [8*32*5]
    float*  base_s = m_s + 8 * 32 * 5;                 // [32*5]
    float*  tau_s  = base_s + 32 * 5;                  // [32]

    const int tid  = threadIdx.x;
    const int warp = tid >> 5;
    const int lane = tid & 31;
    const int rg   = blockIdx.x >> 1;
    const int half = blockIdx.x & 1;
    const int r0   = rg * 32;
    const int b    = r0 >> 12;
    const int n0   = r0 & (N_PTS - 1);
    const int cb   = half * HALF_C;                    // candidate base (in batch)

    // ---- load this half's positions (2048 points) ----
    const float* pb = pos + ((size_t)b * N_PTS + cb) * 3;
    const float4* pb4 = (const float4*)pb;
    for (int g = tid; g < HALF_C / 4; g += SB_THREADS) {
        float4 a = pb4[3*g + 0];
        float4 c = pb4[3*g + 1];
        float4 d = pb4[3*g + 2];
        float4 q;
        q.x = a.x; q.y = a.y; q.z = a.z;
        q.w = -0.5f * fmaf(q.z, q.z, fmaf(q.y, q.y, q.x * q.x));
        pos_s[4*g + 0] = q;
        q.x = a.w; q.y = c.x; q.z = c.y;
        q.w = -0.5f * fmaf(q.z, q.z, fmaf(q.y, q.y, q.x * q.x));
        pos_s[4*g + 1] = q;
        q.x = c.z; q.y = c.w; q.z = d.x;
        q.w = -0.5f * fmaf(q.z, q.z, fmaf(q.y, q.y, q.x * q.x));
        pos_s[4*g + 2] = q;
        q.x = d.y; q.y = d.z; q.z = d.w;
        q.w = -0.5f * fmaf(q.z, q.z, fmaf(q.y, q.y, q.x * q.x));
        pos_s[4*g + 3] = q;
    }
    __syncthreads();

    // ---- this lane's row position (direct from global) ----
    const float* pr = pos + ((size_t)b * N_PTS + n0 + lane) * 3;
    float Px = __ldg(pr), Py = __ldg(pr + 1), Pz = __ldg(pr + 2);
    const float Pw2 = fmaf(Pz, Pz, fmaf(Py, Py, Px * Px));   // |pi|^2

    const float INF = __int_as_float(0x7f800000);
    float s0 = INF, s1 = INF, s2 = INF, s3 = INF, s4 = INF;

    const int base = warp * SB_SLICE;

    // ---- phase 1: unconditional ----
    #pragma unroll 8
    for (int jj = 0; jj < SB_L1; jj++) {
        const int j = base + jj;
        float4 q = pos_s[j];
        float t   = fmaf(Px, q.x, fmaf(Py, q.y, fmaf(Pz, q.z, q.w)));
        float d2c = fmaf(-2.0f, t, Pw2);
        float k   = __int_as_float((__float_as_int(d2c) & 0xFFFFF000) | (cb + j));
        BUBBLE5(k);
    }

    TREEMERGE();

    if (warp == 0) {
        float* bs = base_s + lane * 5;
        bs[0] = s0; bs[1] = s1; bs[2] = s2; bs[3] = s3; bs[4] = s4;
        tau_s[lane] = __int_as_float((__float_as_int(s4) & 0xFFFFF000) + 0x1000);
    }
    __syncthreads();

    const float tau = tau_s[lane];

    // ---- phase 2: filtered ----
    s0 = INF; s1 = INF; s2 = INF; s3 = INF; s4 = INF;
    #pragma unroll 8
    for (int jj = SB_L1; jj < SB_SLICE; jj++) {
        const int j = base + jj;
        float4 q = pos_s[j];
        float t   = fmaf(Px, q.x, fmaf(Py, q.y, fmaf(Pz, q.z, q.w)));
        float d2c = fmaf(-2.0f, t, Pw2);
        if (d2c < tau) {
            float k = __int_as_float((__float_as_int(d2c) & 0xFFFFF000) | (cb + j));
            BUBBLE5(k);
        }
    }

    TREEMERGE();

    if (warp == 0) {
        const float* bs = base_s + lane * 5;
        BUBBLE5(bs[0]); BUBBLE5(bs[1]); BUBBLE5(bs[2]);
        BUBBLE5(bs[3]); BUBBLE5(bs[4]);
        float* dst = Top5_buf + (size_t)(r0 + lane) * 10 + half * 5;
        dst[0] = s0; dst[1] = s1; dst[2] = s2; dst[3] = s3; dst[4] = s4;
    }
}

// ---------------- kernel C: merge halves, exact rerank, weights, gather ----------------
#define GC_THREADS 256
#define GC_WARPS   8           // one row per warp

#define SWP(a,b) { unsigned long long _t; if (a > b) { _t = a; a = b; b = _t; } }

__global__ void __launch_bounds__(GC_THREADS, 8)
finish_gather(const float* __restrict__ pos,
              const float* __restrict__ bias,
              float* __restrict__ out)
{
    const int tid  = threadIdx.x;
    const int warp = tid >> 5;
    const int lane = tid & 31;
    const int row  = blockIdx.x * GC_WARPS + warp;     // global row (b*4096+n)
    const int b    = row >> 12;

    // merge the two per-half top-5 lists (all lanes redundantly; broadcast loads)
    const float* tb = Top5_buf + (size_t)row * 10;
    const float INF = __int_as_float(0x7f800000);
    float s0 = INF, s1 = INF, s2 = INF, s3 = INF, s4 = INF;
    #pragma unroll
    for (int i = 0; i < 10; i++) BUBBLE5(__ldg(&tb[i]));

    // exact difference-form rerank of the 5 survivors
    const float* pr = pos + (size_t)row * 3;
    float Px = __ldg(pr), Py = __ldg(pr + 1), Pz = __ldg(pr + 2);

    float cand[5] = { s0, s1, s2, s3, s4 };
    unsigned long long k[5];
    #pragma unroll
    for (int i = 0; i < 5; i++) {
        int j = __float_as_int(cand[i]) & 0xFFF;       // within-batch index
        const float* pq = pos + ((size_t)b * N_PTS + j) * 3;
        float dx = Px - __ldg(pq);
        float dy = Py - __ldg(pq + 1);
        float dz = Pz - __ldg(pq + 2);
        float d2 = fmaf(dz, dz, fmaf(dy, dy, dx * dx));
        k[i] = ((unsigned long long)__float_as_uint(d2) << 32) | (unsigned)j;
    }
    SWP(k[0],k[1]) SWP(k[3],k[4]) SWP(k[2],k[4]) SWP(k[2],k[3]) SWP(k[0],k[3])
    SWP(k[0],k[2]) SWP(k[1],k[4]) SWP(k[1],k[3]) SWP(k[1],k[2])

    float w0,w1,w2,w3; int i0,i1,i2,i3;
    {
        float d2;
        d2 = __uint_as_float((unsigned)(k[0] >> 32)); w0 = expf(-0.5f*(d2+1e-8f)); i0 = (int)(k[0] & 0xFFFFFFFFull);
        d2 = __uint_as_float((unsigned)(k[1] >> 32)); w1 = expf(-0.5f*(d2+1e-8f)); i1 = (int)(k[1] & 0xFFFFFFFFull);
        d2 = __uint_as_float((unsigned)(k[2] >> 32)); w2 = expf(-0.5f*(d2+1e-8f)); i2 = (int)(k[2] & 0xFFFFFFFFull);
        d2 = __uint_as_float((unsigned)(k[3] >> 32)); w3 = expf(-0.5f*(d2+1e-8f)); i3 = (int)(k[3] & 0xFFFFFFFFull);
    }
    float inv = 1.0f / (((w0 + w1) + w2) + w3 + 1e-8f);
    w0 *= inv; w1 *= inv; w2 *= inv; w3 *= inv;

    // gather Z rows + bias
    const float4* Z4 = (const float4*)Z_buf + (size_t)b * N_PTS * 32;
    float4 acc = __ldg(&((const float4*)bias)[lane]);
    float4 z0 = Z4[(size_t)i0 * 32 + lane];
    float4 z1 = Z4[(size_t)i1 * 32 + lane];
    float4 z2 = Z4[(size_t)i2 * 32 + lane];
    float4 z3 = Z4[(size_t)i3 * 32 + lane];
    acc.x = fmaf(w0,z0.x, fmaf(w1,z1.x, fmaf(w2,z2.x, fmaf(w3,z3.x, acc.x))));
    acc.y = fmaf(w0,z0.y, fmaf(w1,z1.y, fmaf(w2,z2.y, fmaf(w3,z3.y, acc.y))));
    acc.z = fmaf(w0,z0.z, fmaf(w1,z1.z, fmaf(w2,z2.z, fmaf(w3,z3.z, acc.z))));
    acc.w = fmaf(w0,z0.w, fmaf(w1,z1.w, fmaf(w2,z2.w, fmaf(w3,z3.w, acc.w))));
    ((float4*)out)[(size_t)row * 32 + lane] = acc;
}

extern "C" void kernel_launch(void* const* d_in, const int* in_sizes, int n_in,
                              void* d_out, int out_size)
{
    const float* x    = (const float*)d_in[0];
    const float* pos  = (const float*)d_in[1];
    const float* W    = (const float*)d_in[2];
    const float* bias = (const float*)d_in[3];
    float* out        = (float*)d_out;

    const int rows = in_sizes[1] / 3;                  // B * N = 8192

    // A: Z = x @ W
    gemm_xw<<<rows / GA_ROWS, GA_THREADS>>>(x, W);

    // B: per-(32-row, half) top-5 scan
    const size_t smemB = (size_t)HALF_C * 16           // pos_s        32768
                       + 8 * 32 * 5 * 4                // m_s           5120
                       + 32 * 5 * 4                    // base_s         640
                       + 32 * 4;                       // tau_s          128
    cudaFuncSetAttribute(scan_topk, cudaFuncAttributeMaxDynamicSharedMemorySize, (int)smemB);
    scan_topk<<<(rows / 32) * 2, SB_THREADS, smemB>>>(pos);

    // C: merge + rerank + gather
    finish_gather<<<rows / GC_WARPS, GC_THREADS>>>(pos, bias, out);
}

// round 8
// speedup vs baseline: 1.9669x; 1.9669x over previous
#include <cuda_runtime.h>
#include <cstdint>

#define N_PTS   4096
#define DIM     128
#define TOPK    4

// ---------------- global scratch ----------------
__device__ float Top5_buf[2 * N_PTS * 10];      // per (row, half) top-5 packed keys

#define BUBBLE5(k)                                            \
    { float _t, _k = (k);                                     \
      _t = fminf(s0, _k); _k = fmaxf(s0, _k); s0 = _t;        \
      _t = fminf(s1, _k); _k = fmaxf(s1, _k); s1 = _t;        \
      _t = fminf(s2, _k); _k = fmaxf(s2, _k); s2 = _t;        \
      _t = fminf(s3, _k); _k = fmaxf(s3, _k); s3 = _t;        \
      s4 = fminf(s4, _k); }

#define SWP(a,b) { unsigned long long _t; if (a > b) { _t = a; a = b; b = _t; } }

// ---------------- kernel 1: per-(32-row, 2048-cand-half) top-5 scan ----------------
// blockIdx.x -> (row_group, half). 16 warps; row-per-lane; slice 128 cands/warp.
// Phase 1: first 32 of each slice unconditional -> tau (5th of 512 samples).
// Phase 2: remaining 96 filtered. Tree-merge; warp 0 writes 5 packed keys/row.

#define SB_THREADS 512
#define SB_WARPS   16
#define HALF_C     (N_PTS / 2)              // 2048
#define SB_SLICE   (HALF_C / SB_WARPS)      // 128
#define SB_L1      32

#define TREEMERGE()                                                        \
    _Pragma("unroll")                                                      \
    for (int step = 8; step >= 1; step >>= 1) {                            \
        if (warp >= step && warp < 2 * step) {                             \
            float* m = m_s + ((warp - step) * 32 + lane) * 5;              \
            m[0] = s0; m[1] = s1; m[2] = s2; m[3] = s3; m[4] = s4;         \
        }                                                                  \
        __syncthreads();                                                   \
        if (warp < step) {                                                 \
            const float* m = m_s + (warp * 32 + lane) * 5;                 \
            BUBBLE5(m[0]); BUBBLE5(m[1]); BUBBLE5(m[2]);                   \
            BUBBLE5(m[3]); BUBBLE5(m[4]);                                  \
        }                                                                  \
        __syncthreads();                                                   \
    }

__global__ void __launch_bounds__(SB_THREADS, 3)
scan_topk(const float* __restrict__ pos)
{
    extern __shared__ float smemB[];
    float4* pos_s  = (float4*)smemB;                   // [2048] .w = -0.5*|p|^2
    float*  m_s    = (float*)(pos_s + HALF_C);         // [8*32*5]
    float*  base_s = m_s + 8 * 32 * 5;                 // [32*5]
    float*  tau_s  = base_s + 32 * 5;                  // [32]

    const int tid  = threadIdx.x;
    const int warp = tid >> 5;
    const int lane = tid & 31;
    const int rg   = blockIdx.x >> 1;
    const int half = blockIdx.x & 1;
    const int r0   = rg * 32;
    const int b    = r0 >> 12;
    const int n0   = r0 & (N_PTS - 1);
    const int cb   = half * HALF_C;                    // candidate base (in batch)

    // ---- load this half's positions (2048 points) ----
    const float* pb = pos + ((size_t)b * N_PTS + cb) * 3;
    const float4* pb4 = (const float4*)pb;
    for (int g = tid; g < HALF_C / 4; g += SB_THREADS) {
        float4 a = pb4[3*g + 0];
        float4 c = pb4[3*g + 1];
        float4 d = pb4[3*g + 2];
        float4 q;
        q.x = a.x; q.y = a.y; q.z = a.z;
        q.w = -0.5f * fmaf(q.z, q.z, fmaf(q.y, q.y, q.x * q.x));
        pos_s[4*g + 0] = q;
        q.x = a.w; q.y = c.x; q.z = c.y;
        q.w = -0.5f * fmaf(q.z, q.z, fmaf(q.y, q.y, q.x * q.x));
        pos_s[4*g + 1] = q;
        q.x = c.z; q.y = c.w; q.z = d.x;
        q.w = -0.5f * fmaf(q.z, q.z, fmaf(q.y, q.y, q.x * q.x));
        pos_s[4*g + 2] = q;
        q.x = d.y; q.y = d.z; q.z = d.w;
        q.w = -0.5f * fmaf(q.z, q.z, fmaf(q.y, q.y, q.x * q.x));
        pos_s[4*g + 3] = q;
    }
    __syncthreads();

    // ---- this lane's row position ----
    const float* pr = pos + ((size_t)b * N_PTS + n0 + lane) * 3;
    float Px = __ldg(pr), Py = __ldg(pr + 1), Pz = __ldg(pr + 2);
    const float Pw2 = fmaf(Pz, Pz, fmaf(Py, Py, Px * Px));   // |pi|^2

    const float INF = __int_as_float(0x7f800000);
    float s0 = INF, s1 = INF, s2 = INF, s3 = INF, s4 = INF;

    const int base = warp * SB_SLICE;

    // ---- phase 1: unconditional (32 cands/warp -> 512 samples/half) ----
    #pragma unroll 8
    for (int jj = 0; jj < SB_L1; jj++) {
        const int j = base + jj;
        float4 q = pos_s[j];
        float t   = fmaf(Px, q.x, fmaf(Py, q.y, fmaf(Pz, q.z, q.w)));
        float d2c = fmaf(-2.0f, t, Pw2);
        float k   = __int_as_float((__float_as_int(d2c) & 0xFFFFF000) | (cb + j));
        BUBBLE5(k);
    }

    TREEMERGE();

    if (warp == 0) {
        float* bs = base_s + lane * 5;
        bs[0] = s0; bs[1] = s1; bs[2] = s2; bs[3] = s3; bs[4] = s4;
        tau_s[lane] = __int_as_float((__float_as_int(s4) & 0xFFFFF000) + 0x1000);
    }
    __syncthreads();

    const float tau = tau_s[lane];

    // ---- phase 2: filtered ----
    s0 = INF; s1 = INF; s2 = INF; s3 = INF; s4 = INF;
    #pragma unroll 8
    for (int jj = SB_L1; jj < SB_SLICE; jj++) {
        const int j = base + jj;
        float4 q = pos_s[j];
        float t   = fmaf(Px, q.x, fmaf(Py, q.y, fmaf(Pz, q.z, q.w)));
        float d2c = fmaf(-2.0f, t, Pw2);
        if (d2c < tau) {
            float k = __int_as_float((__float_as_int(d2c) & 0xFFFFF000) | (cb + j));
            BUBBLE5(k);
        }
    }

    TREEMERGE();

    if (warp == 0) {
        const float* bs = base_s + lane * 5;
        BUBBLE5(bs[0]); BUBBLE5(bs[1]); BUBBLE5(bs[2]);
        BUBBLE5(bs[3]); BUBBLE5(bs[4]);
        float* dst = Top5_buf + (size_t)(r0 + lane) * 10 + half * 5;
        dst[0] = s0; dst[1] = s1; dst[2] = s2; dst[3] = s3; dst[4] = s4;
    }
}

// ---------------- kernel 2: fused merge + rerank + gather + GEMM ----------------
// Block: 512 thr, 32 rows. Threads 0-31 do rerank/weights while 32-511 load W_s.
// Then all threads gather y = sum_r w_r x[i_r] into smem; then smem GEMM y@W + b.

#define FB_THREADS 512

__global__ void __launch_bounds__(FB_THREADS, 2)
finish_fused(const float* __restrict__ pos,
             const float* __restrict__ x,
             const float* __restrict__ W,
             const float* __restrict__ bias,
             float* __restrict__ out)
{
    extern __shared__ float smemC[];
    float4* W_s   = (float4*)smemC;                    // [128*32]  64 KB
    float*  y_s   = (float*)(W_s + DIM * 32);          // [32*128]  16 KB
    float*  w_s   = y_s + 32 * DIM;                    // [32*4]
    int*    idx_s = (int*)(w_s + 32 * 4);              // [32*4]

    const int tid  = threadIdx.x;
    const int r0   = blockIdx.x * 32;
    const int b    = r0 >> 12;

    if (tid < 32) {
        // ---- phase A: merge halves, exact rerank, weights (1 thread / row) ----
        const int row = r0 + tid;
        const float* tb = Top5_buf + (size_t)row * 10;
        const float INF = __int_as_float(0x7f800000);
        float s0 = INF, s1 = INF, s2 = INF, s3 = INF, s4 = INF;
        #pragma unroll
        for (int i = 0; i < 10; i++) BUBBLE5(tb[i]);

        const float* pr = pos + (size_t)row * 3;
        float Px = pr[0], Py = pr[1], Pz = pr[2];

        float cand[5] = { s0, s1, s2, s3, s4 };
        unsigned long long k[5];
        #pragma unroll
        for (int i = 0; i < 5; i++) {
            int j = __float_as_int(cand[i]) & 0xFFF;
            const float* pq = pos + ((size_t)b * N_PTS + j) * 3;
            float dx = Px - pq[0], dy = Py - pq[1], dz = Pz - pq[2];
            float d2 = fmaf(dz, dz, fmaf(dy, dy, dx * dx));
            k[i] = ((unsigned long long)__float_as_uint(d2) << 32) | (unsigned)j;
        }
        SWP(k[0],k[1]) SWP(k[3],k[4]) SWP(k[2],k[4]) SWP(k[2],k[3]) SWP(k[0],k[3])
        SWP(k[0],k[2]) SWP(k[1],k[4]) SWP(k[1],k[3]) SWP(k[1],k[2])

        float wgt[TOPK];
        #pragma unroll
        for (int r = 0; r < TOPK; r++) {
            float d2 = __uint_as_float((unsigned)(k[r] >> 32));
            wgt[r]   = expf(-0.5f * (d2 + 1e-8f));
            idx_s[tid * TOPK + r] = (int)(k[r] & 0xFFFFFFFFull);
        }
        float inv = 1.0f / (((wgt[0] + wgt[1]) + wgt[2]) + wgt[3] + 1e-8f);
        #pragma unroll
        for (int r = 0; r < TOPK; r++) w_s[tid * TOPK + r] = wgt[r] * inv;
    } else {
        // ---- phase A': cooperative W load (480 threads) ----
        const float4* W4 = (const float4*)W;
        for (int i = tid - 32; i < DIM * 32; i += FB_THREADS - 32)
            W_s[i] = __ldg(&W4[i]);
    }
    __syncthreads();

    // ---- phase B: gather y rows into smem (2 float4 slots / thread) ----
    {
        const float4* xb = (const float4*)x + (size_t)b * N_PTS * 32;
        float4* y4 = (float4*)y_s;
        #pragma unroll
        for (int s = tid; s < 32 * 32; s += FB_THREADS) {
            const int row = s >> 5, c = s & 31;
            float w0 = w_s[row*4+0], w1 = w_s[row*4+1],
                  w2 = w_s[row*4+2], w3 = w_s[row*4+3];
            float4 x0 = xb[(size_t)idx_s[row*4+0] * 32 + c];
            float4 x1 = xb[(size_t)idx_s[row*4+1] * 32 + c];
            float4 x2 = xb[(size_t)idx_s[row*4+2] * 32 + c];
            float4 x3 = xb[(size_t)idx_s[row*4+3] * 32 + c];
            float4 acc;
            acc.x = fmaf(w0,x0.x, fmaf(w1,x1.x, fmaf(w2,x2.x, w3*x3.x)));
            acc.y = fmaf(w0,x0.y, fmaf(w1,x1.y, fmaf(w2,x2.y, w3*x3.y)));
            acc.z = fmaf(w0,x0.z, fmaf(w1,x1.z, fmaf(w2,x2.z, w3*x3.z)));
            acc.w = fmaf(w0,x0.w, fmaf(w1,x1.w, fmaf(w2,x2.w, w3*x3.w)));
            y4[s] = acc;
        }
    }
    __syncthreads();

    // ---- phase C: GEMM  out[r0..r0+31] = y @ W + b  (16 warps x 2 rows) ----
    const int warp = tid >> 5;
    const int lane = tid & 31;
    const float* ya = y_s + (warp * 2 + 0) * DIM;
    const float* yb = y_s + (warp * 2 + 1) * DIM;

    float4 bv = __ldg(&((const float4*)bias)[lane]);
    float4 a0 = bv, a1 = bv;

    #pragma unroll 4
    for (int d = 0; d < DIM; d++) {
        float4 wv = W_s[d * 32 + lane];
        float f0 = ya[d];
        float f1 = yb[d];
        a0.x = fmaf(f0, wv.x, a0.x); a0.y = fmaf(f0, wv.y, a0.y);
        a0.z = fmaf(f0, wv.z, a0.z); a0.w = fmaf(f0, wv.w, a0.w);
        a1.x = fmaf(f1, wv.x, a1.x); a1.y = fmaf(f1, wv.y, a1.y);
        a1.z = fmaf(f1, wv.z, a1.z); a1.w = fmaf(f1, wv.w, a1.w);
    }

    float4* out4 = (float4*)out;
    out4[(size_t)(r0 + warp * 2 + 0) * 32 + lane] = a0;
    out4[(size_t)(r0 + warp * 2 + 1) * 32 + lane] = a1;
}

extern "C" void kernel_launch(void* const* d_in, const int* in_sizes, int n_in,
                              void* d_out, int out_size)
{
    const float* x    = (const float*)d_in[0];
    const float* pos  = (const float*)d_in[1];
    const float* W    = (const float*)d_in[2];
    const float* bias = (const float*)d_in[3];
    float* out        = (float*)d_out;

    const int rows = in_sizes[1] / 3;                  // B * N = 8192

    // K1: per-(32-row, half) top-5 scan
    const size_t smemB = (size_t)HALF_C * 16           // pos_s        32768
                       + 8 * 32 * 5 * 4                // m_s           5120
                       + 32 * 5 * 4                    // base_s         640
                       + 32 * 4;                       // tau_s          128
    cudaFuncSetAttribute(scan_topk, cudaFuncAttributeMaxDynamicSharedMemorySize, (int)smemB);
    scan_topk<<<(rows / 32) * 2, SB_THREADS, smemB>>>(pos);

    // K2: merge + rerank + gather + GEMM
    const size_t smemC = (size_t)DIM * 32 * 16         // W_s          65536
                       + (size_t)32 * DIM * 4          // y_s          16384
                       + 32 * 4 * 4                    // w_s            512
                       + 32 * 4 * 4;                   // idx_s          512
    cudaFuncSetAttribute(finish_fused, cudaFuncAttributeMaxDynamicSharedMemorySize, (int)smemC);
    finish_fused<<<rows / 32, FB_THREADS, smemC>>>(pos, x, W, bias, out);
}

// round 9
// speedup vs baseline: 2.0514x; 1.0430x over previous
#include <cuda_runtime.h>
#include <cstdint>

#define N_PTS   4096
#define DIM     128
#define TOPK    4

// ---------------- global scratch ----------------
__device__ float Z_buf[2 * N_PTS * DIM];        // x @ W  (4 MB)
__device__ float Top5_buf[2 * N_PTS * 10];      // per (row, half) top-5 packed keys

#define BUBBLE5(k)                                            \
    { float _t, _k = (k);                                     \
      _t = fminf(s0, _k); _k = fmaxf(s0, _k); s0 = _t;        \
      _t = fminf(s1, _k); _k = fmaxf(s1, _k); s1 = _t;        \
      _t = fminf(s2, _k); _k = fmaxf(s2, _k); s2 = _t;        \
      _t = fminf(s3, _k); _k = fmaxf(s3, _k); s3 = _t;        \
      s4 = fminf(s4, _k); }

#define SWP(a,b) { unsigned long long _t; if (a > b) { _t = a; a = b; b = _t; } }

// ---------------- kernel 1: block-specialized scan + GEMM ----------------
// Blocks [0, 512): top-5 scan per (32-row group, 2048-cand half)  [R8 logic]
// Blocks [512, 640): Z = x @ W, 64 rows per block, 16 warps x 4 rows

#define K1_THREADS 512
#define SB_WARPS   16
#define HALF_C     (N_PTS / 2)              // 2048
#define SB_SLICE   (HALF_C / SB_WARPS)      // 128
#define SB_L1      32
#define SCAN_BLOCKS 512                     // (8192/32) * 2
#define GEMM_ROWS   64

#define TREEMERGE()                                                        \
    _Pragma("unroll")                                                      \
    for (int step = 8; step >= 1; step >>= 1) {                            \
        if (warp >= step && warp < 2 * step) {                             \
            float* m = m_s + ((warp - step) * 32 + lane) * 5;              \
            m[0] = s0; m[1] = s1; m[2] = s2; m[3] = s3; m[4] = s4;         \
        }                                                                  \
        __syncthreads();                                                   \
        if (warp < step) {                                                 \
            const float* m = m_s + (warp * 32 + lane) * 5;                 \
            BUBBLE5(m[0]); BUBBLE5(m[1]); BUBBLE5(m[2]);                   \
            BUBBLE5(m[3]); BUBBLE5(m[4]);                                  \
        }                                                                  \
        __syncthreads();                                                   \
    }

__global__ void __launch_bounds__(K1_THREADS, 2)
scan_and_gemm(const float* __restrict__ pos,
              const float* __restrict__ x,
              const float* __restrict__ W)
{
    extern __shared__ float smem[];
    const int tid  = threadIdx.x;
    const int warp = tid >> 5;
    const int lane = tid & 31;

    if (blockIdx.x < SCAN_BLOCKS) {
        // ================= SCAN ROLE =================
        float4* pos_s  = (float4*)smem;                    // [2048] .w = -0.5|p|^2
        float*  m_s    = (float*)(pos_s + HALF_C);         // [8*32*5]
        float*  base_s = m_s + 8 * 32 * 5;                 // [32*5]
        float*  tau_s  = base_s + 32 * 5;                  // [32]

        const int rg   = blockIdx.x >> 1;
        const int half = blockIdx.x & 1;
        const int r0   = rg * 32;
        const int b    = r0 >> 12;
        const int n0   = r0 & (N_PTS - 1);
        const int cb   = half * HALF_C;

        const float* pb = pos + ((size_t)b * N_PTS + cb) * 3;
        const float4* pb4 = (const float4*)pb;
        for (int g = tid; g < HALF_C / 4; g += K1_THREADS) {
            float4 a = pb4[3*g + 0];
            float4 c = pb4[3*g + 1];
            float4 d = pb4[3*g + 2];
            float4 q;
            q.x = a.x; q.y = a.y; q.z = a.z;
            q.w = -0.5f * fmaf(q.z, q.z, fmaf(q.y, q.y, q.x * q.x));
            pos_s[4*g + 0] = q;
            q.x = a.w; q.y = c.x; q.z = c.y;
            q.w = -0.5f * fmaf(q.z, q.z, fmaf(q.y, q.y, q.x * q.x));
            pos_s[4*g + 1] = q;
            q.x = c.z; q.y = c.w; q.z = d.x;
            q.w = -0.5f * fmaf(q.z, q.z, fmaf(q.y, q.y, q.x * q.x));
            pos_s[4*g + 2] = q;
            q.x = d.y; q.y = d.z; q.z = d.w;
            q.w = -0.5f * fmaf(q.z, q.z, fmaf(q.y, q.y, q.x * q.x));
            pos_s[4*g + 3] = q;
        }
        __syncthreads();

        const float* pr = pos + ((size_t)b * N_PTS + n0 + lane) * 3;
        float Px = __ldg(pr), Py = __ldg(pr + 1), Pz = __ldg(pr + 2);
        const float Pw2 = fmaf(Pz, Pz, fmaf(Py, Py, Px * Px));

        const float INF = __int_as_float(0x7f800000);
        float s0 = INF, s1 = INF, s2 = INF, s3 = INF, s4 = INF;

        const int base = warp * SB_SLICE;

        #pragma unroll 8
        for (int jj = 0; jj < SB_L1; jj++) {
            const int j = base + jj;
            float4 q = pos_s[j];
            float t   = fmaf(Px, q.x, fmaf(Py, q.y, fmaf(Pz, q.z, q.w)));
            float d2c = fmaf(-2.0f, t, Pw2);
            float k   = __int_as_float((__float_as_int(d2c) & 0xFFFFF000) | (cb + j));
            BUBBLE5(k);
        }

        TREEMERGE();

        if (warp == 0) {
            float* bs = base_s + lane * 5;
            bs[0] = s0; bs[1] = s1; bs[2] = s2; bs[3] = s3; bs[4] = s4;
            tau_s[lane] = __int_as_float((__float_as_int(s4) & 0xFFFFF000) + 0x1000);
        }
        __syncthreads();

        const float tau = tau_s[lane];

        s0 = INF; s1 = INF; s2 = INF; s3 = INF; s4 = INF;
        #pragma unroll 8
        for (int jj = SB_L1; jj < SB_SLICE; jj++) {
            const int j = base + jj;
            float4 q = pos_s[j];
            float t   = fmaf(Px, q.x, fmaf(Py, q.y, fmaf(Pz, q.z, q.w)));
            float d2c = fmaf(-2.0f, t, Pw2);
            if (d2c < tau) {
                float k = __int_as_float((__float_as_int(d2c) & 0xFFFFF000) | (cb + j));
                BUBBLE5(k);
            }
        }

        TREEMERGE();

        if (warp == 0) {
            const float* bs = base_s + lane * 5;
            BUBBLE5(bs[0]); BUBBLE5(bs[1]); BUBBLE5(bs[2]);
            BUBBLE5(bs[3]); BUBBLE5(bs[4]);
            float* dst = Top5_buf + (size_t)(r0 + lane) * 10 + half * 5;
            dst[0] = s0; dst[1] = s1; dst[2] = s2; dst[3] = s3; dst[4] = s4;
        }
    } else {
        // ================= GEMM ROLE: Z = x @ W =================
        float4* W_s = (float4*)smem;                       // [128*32] 64 KB
        float*  x_s = (float*)(W_s + DIM * 32);            // [64*128] 32 KB

        const int g0 = (int)(blockIdx.x - SCAN_BLOCKS) * GEMM_ROWS;

        const float4* W4 = (const float4*)W;
        #pragma unroll
        for (int i = tid; i < DIM * 32; i += K1_THREADS) W_s[i] = __ldg(&W4[i]);

        const float4* xg = (const float4*)x + (size_t)g0 * 32;
        float4* xs4 = (float4*)x_s;
        #pragma unroll
        for (int i = tid; i < GEMM_ROWS * 32; i += K1_THREADS) xs4[i] = __ldg(&xg[i]);
        __syncthreads();

        const float* xr = x_s + warp * 4 * DIM;            // 4 rows per warp

        float4 a0 = make_float4(0.f,0.f,0.f,0.f);
        float4 a1 = a0, a2 = a0, a3 = a0;

        #pragma unroll 4
        for (int d = 0; d < DIM; d++) {
            float4 wv = W_s[d * 32 + lane];
            float y0 = xr[d];
            float y1 = xr[d + DIM];
            float y2 = xr[d + 2*DIM];
            float y3 = xr[d + 3*DIM];
            a0.x = fmaf(y0, wv.x, a0.x); a0.y = fmaf(y0, wv.y, a0.y);
            a0.z = fmaf(y0, wv.z, a0.z); a0.w = fmaf(y0, wv.w, a0.w);
            a1.x = fmaf(y1, wv.x, a1.x); a1.y = fmaf(y1, wv.y, a1.y);
            a1.z = fmaf(y1, wv.z, a1.z); a1.w = fmaf(y1, wv.w, a1.w);
            a2.x = fmaf(y2, wv.x, a2.x); a2.y = fmaf(y2, wv.y, a2.y);
            a2.z = fmaf(y2, wv.z, a2.z); a2.w = fmaf(y2, wv.w, a2.w);
            a3.x = fmaf(y3, wv.x, a3.x); a3.y = fmaf(y3, wv.y, a3.y);
            a3.z = fmaf(y3, wv.z, a3.z); a3.w = fmaf(y3, wv.w, a3.w);
        }

        float4* Z4 = (float4*)Z_buf;
        const size_t r = (size_t)g0 + warp * 4;
        Z4[(r + 0) * 32 + lane] = a0;
        Z4[(r + 1) * 32 + lane] = a1;
        Z4[(r + 2) * 32 + lane] = a2;
        Z4[(r + 3) * 32 + lane] = a3;
    }
}

// ---------------- kernel 2: merge halves, exact rerank, weights, gather ----------------
#define GC_THREADS 256
#define GC_WARPS   8           // one row per warp

__global__ void __launch_bounds__(GC_THREADS, 8)
finish_gather(const float* __restrict__ pos,
              const float* __restrict__ bias,
              float* __restrict__ out)
{
    const int tid  = threadIdx.x;
    const int warp = tid >> 5;
    const int lane = tid & 31;
    const int row  = blockIdx.x * GC_WARPS + warp;     // global row (b*4096+n)
    const int b    = row >> 12;

    // merge the two per-half top-5 lists (broadcast loads, all lanes redundant)
    const float* tb = Top5_buf + (size_t)row * 10;
    const float INF = __int_as_float(0x7f800000);
    float s0 = INF, s1 = INF, s2 = INF, s3 = INF, s4 = INF;
    #pragma unroll
    for (int i = 0; i < 10; i++) BUBBLE5(__ldg(&tb[i]));

    // exact difference-form rerank of the 5 survivors
    const float* pr = pos + (size_t)row * 3;
    float Px = __ldg(pr), Py = __ldg(pr + 1), Pz = __ldg(pr + 2);

    float cand[5] = { s0, s1, s2, s3, s4 };
    unsigned long long k[5];
    #pragma unroll
    for (int i = 0; i < 5; i++) {
        int j = __float_as_int(cand[i]) & 0xFFF;       // within-batch index
        const float* pq = pos + ((size_t)b * N_PTS + j) * 3;
        float dx = Px - __ldg(pq);
        float dy = Py - __ldg(pq + 1);
        float dz = Pz - __ldg(pq + 2);
        float d2 = fmaf(dz, dz, fmaf(dy, dy, dx * dx));
        k[i] = ((unsigned long long)__float_as_uint(d2) << 32) | (unsigned)j;
    }
    SWP(k[0],k[1]) SWP(k[3],k[4]) SWP(k[2],k[4]) SWP(k[2],k[3]) SWP(k[0],k[3])
    SWP(k[0],k[2]) SWP(k[1],k[4]) SWP(k[1],k[3]) SWP(k[1],k[2])

    float w0,w1,w2,w3; int i0,i1,i2,i3;
    {
        float d2;
        d2 = __uint_as_float((unsigned)(k[0] >> 32)); w0 = expf(-0.5f*(d2+1e-8f)); i0 = (int)(k[0] & 0xFFFFFFFFull);
        d2 = __uint_as_float((unsigned)(k[1] >> 32)); w1 = expf(-0.5f*(d2+1e-8f)); i1 = (int)(k[1] & 0xFFFFFFFFull);
        d2 = __uint_as_float((unsigned)(k[2] >> 32)); w2 = expf(-0.5f*(d2+1e-8f)); i2 = (int)(k[2] & 0xFFFFFFFFull);
        d2 = __uint_as_float((unsigned)(k[3] >> 32)); w3 = expf(-0.5f*(d2+1e-8f)); i3 = (int)(k[3] & 0xFFFFFFFFull);
    }
    float inv = 1.0f / (((w0 + w1) + w2) + w3 + 1e-8f);
    w0 *= inv; w1 *= inv; w2 *= inv; w3 *= inv;

    // gather Z rows + bias
    const float4* Z4 = (const float4*)Z_buf + (size_t)b * N_PTS * 32;
    float4 acc = __ldg(&((const float4*)bias)[lane]);
    float4 z0 = Z4[(size_t)i0 * 32 + lane];
    float4 z1 = Z4[(size_t)i1 * 32 + lane];
    float4 z2 = Z4[(size_t)i2 * 32 + lane];
    float4 z3 = Z4[(size_t)i3 * 32 + lane];
    acc.x = fmaf(w0,z0.x, fmaf(w1,z1.x, fmaf(w2,z2.x, fmaf(w3,z3.x, acc.x))));
    acc.y = fmaf(w0,z0.y, fmaf(w1,z1.y, fmaf(w2,z2.y, fmaf(w3,z3.y, acc.y))));
    acc.z = fmaf(w0,z0.z, fmaf(w1,z1.z, fmaf(w2,z2.z, fmaf(w3,z3.z, acc.z))));
    acc.w = fmaf(w0,z0.w, fmaf(w1,z1.w, fmaf(w2,z2.w, fmaf(w3,z3.w, acc.w))));
    ((float4*)out)[(size_t)row * 32 + lane] = acc;
}

extern "C" void kernel_launch(void* const* d_in, const int* in_sizes, int n_in,
                              void* d_out, int out_size)
{
    const float* x    = (const float*)d_in[0];
    const float* pos  = (const float*)d_in[1];
    const float* W    = (const float*)d_in[2];
    const float* bias = (const float*)d_in[3];
    float* out        = (float*)d_out;

    const int rows = in_sizes[1] / 3;                  // B * N = 8192

    // K1: 512 scan blocks + 128 GEMM blocks, one launch (overlapped roles)
    const size_t smemScan = (size_t)HALF_C * 16 + 8*32*5*4 + 32*5*4 + 32*4;   // ~38.7 KB
    const size_t smemGemm = (size_t)DIM * 32 * 16 + (size_t)GEMM_ROWS * DIM * 4; // 96 KB
    const size_t smem1 = smemScan > smemGemm ? smemScan : smemGemm;
    cudaFuncSetAttribute(scan_and_gemm, cudaFuncAttributeMaxDynamicSharedMemorySize, (int)smem1);
    const int scan_blocks = (rows / 32) * 2;           // 512
    const int gemm_blocks = rows / GEMM_ROWS;          // 128
    scan_and_gemm<<<scan_blocks + gemm_blocks, K1_THREADS, smem1>>>(pos, x, W);

    // K2: merge + rerank + gather
    finish_gather<<<rows / GC_WARPS, GC_THREADS>>>(pos, bias, out);
}